// round 4
// baseline (speedup 1.0000x reference)
#include <cuda_runtime.h>
#include <math.h>

#define T_STEPS 2048
#define ISZ 256
#define HSZ 512
#define BSZ 64
#define NB 128
#define TPB 512
#define KS 8
#define BN_EPS 1e-5f

#define WIH_STR 264   // 256+8: 8 mod 32 banks, 16B aligned
#define WHH_STR 520   // 512+8

typedef unsigned long long ull;

// ---------------- shared memory layout ----------------
struct __align__(16) Smem {
    float buf[HSZ * BSZ];        // 131072 B: x tile (lower half) / h tile
    float red[KS * 1024];        // 32768 B: per-kslice partials (natural layout)
    float Whh[16 * WHH_STR];     // 33280 B
    float Wih[16 * WIH_STR];     // 16896 B
    float aRed[1024];            // natural [row16][col64]
    float bRed[1024];
    float sa_scale[16], sa_shift[16], sb_scale[16], sb_shift[16];
    float bias16[16], gi[16], bi[16], gh[16], bh[16];
    float gc[4], bc[4];
    float csum[8], csq[8];
    float cscale[4], cshift[4];
};

// ---------------- device globals ----------------
__device__ float g_h[2][HSZ * BSZ];
__device__ unsigned long long g_arrive = 0ULL;
__device__ volatile unsigned long long g_release = 0ULL;

// ---------------- helpers ----------------
__device__ __forceinline__ ull dup2(float w) {
    ull r;
    unsigned u = __float_as_uint(w);
    asm("mov.b64 %0, {%1, %1};" : "=l"(r) : "r"(u));
    return r;
}
__device__ __forceinline__ void fma2(ull& d, ull a, ull b) {
    asm("fma.rn.f32x2 %0, %1, %2, %0;" : "+l"(d) : "l"(a), "l"(b));
}
__device__ __forceinline__ void cp_async16(void* smem_dst, const void* gsrc) {
    unsigned s = (unsigned)__cvta_generic_to_shared(smem_dst);
    asm volatile("cp.async.cg.shared.global [%0], [%1], 16;" :: "r"(s), "l"(gsrc));
}
__device__ __forceinline__ void cp_commit() { asm volatile("cp.async.commit_group;"); }
template <int N>
__device__ __forceinline__ void cp_wait() { asm volatile("cp.async.wait_group %0;" :: "n"(N)); }

__device__ __forceinline__ float sigm(float x) { return 1.0f / (1.0f + __expf(-x)); }
__device__ __forceinline__ float tanh_fast(float x) {
    // tanh(x) = 2*sigmoid(2x) - 1
    return 2.0f / (1.0f + __expf(-2.0f * x)) - 1.0f;
}

__device__ __forceinline__ void grid_barrier() {
    __syncthreads();
    if (threadIdx.x == 0) {
        __threadfence();
        unsigned long long a = atomicAdd(&g_arrive, 1ULL);
        unsigned long long target = (a / NB + 1ULL) * NB;
        if (a % NB == NB - 1) {
            __threadfence();
            g_release = target;
        } else {
            while (g_release < target) { }
        }
    }
    __syncthreads();
}

// GEMM micro-kernel: rows {rowg+4ri}, colpairs {cpg, cpg+16}
template <int KLEN, int WSTR>
__device__ __forceinline__ void dot_phase(ull acc[4][2], const float* __restrict__ W,
                                          const float* __restrict__ vsrc,
                                          int kb, int rowg, int cpg)
{
    const float* w0p = W + (rowg + 0)  * WSTR + kb;
    const float* w1p = W + (rowg + 4)  * WSTR + kb;
    const float* w2p = W + (rowg + 8)  * WSTR + kb;
    const float* w3p = W + (rowg + 12) * WSTR + kb;
    const ull* vb = (const ull*)vsrc + (size_t)kb * 32 + cpg;
    #pragma unroll 2
    for (int k4 = 0; k4 < KLEN; k4 += 4) {
        float4 w0 = *(const float4*)(w0p + k4);
        float4 w1 = *(const float4*)(w1p + k4);
        float4 w2 = *(const float4*)(w2p + k4);
        float4 w3 = *(const float4*)(w3p + k4);
        const float* f0 = (const float*)&w0;
        const float* f1 = (const float*)&w1;
        const float* f2 = (const float*)&w2;
        const float* f3 = (const float*)&w3;
        #pragma unroll
        for (int kk = 0; kk < 4; ++kk) {
            const ull* vp = vb + (size_t)(k4 + kk) * 32;
            ull v0 = vp[0], v1 = vp[16];
            ull d0 = dup2(f0[kk]);
            ull d1 = dup2(f1[kk]);
            ull d2 = dup2(f2[kk]);
            ull d3 = dup2(f3[kk]);
            fma2(acc[0][0], d0, v0); fma2(acc[0][1], d0, v1);
            fma2(acc[1][0], d1, v0); fma2(acc[1][1], d1, v1);
            fma2(acc[2][0], d2, v0); fma2(acc[2][1], d2, v1);
            fma2(acc[3][0], d3, v0); fma2(acc[3][1], d3, v1);
        }
    }
}

// natural layout: redU[ksl*512 + row*32 + cp]
__device__ __forceinline__ void store_partials(Smem& s, ull acc[4][2], int ksl,
                                               int rowg, int cpg) {
    ull* redU = (ull*)s.red;
    #pragma unroll
    for (int ri = 0; ri < 4; ++ri) {
        int base = ksl * 512 + (rowg + 4 * ri) * 32;
        redU[base + cpg]      = acc[ri][0];
        redU[base + cpg + 16] = acc[ri][1];
    }
}

// reduce KS slices: thread tid handles one ull slot -> dst natural [row][col]
__device__ __forceinline__ void reduce_partials(Smem& s, float* dst, int tid) {
    const float2* rp = (const float2*)s.red;
    float2 a = rp[tid];
    #pragma unroll
    for (int ss = 1; ss < KS; ++ss) {
        float2 p = rp[ss * 512 + tid];
        a.x += p.x; a.y += p.y;
    }
    ((float2*)dst)[tid] = a;
}

// ---------------- kernel ----------------
__global__ void __launch_bounds__(TPB, 1)
bn_lstm_kernel(const float* __restrict__ x,
               const float* __restrict__ wih,
               const float* __restrict__ whh,
               const float* __restrict__ bias,
               const float* __restrict__ gih, const float* __restrict__ bih,
               const float* __restrict__ ghh, const float* __restrict__ bhh,
               const float* __restrict__ gcc, const float* __restrict__ bcc,
               float* __restrict__ out)
{
    extern __shared__ char smem_raw[];
    Smem& s = *reinterpret_cast<Smem*>(smem_raw);

    const int tid = threadIdx.x;
    const int bid = blockIdx.x;
    const int j0  = 4 * bid;

    // dot-phase mapping: 64 threads per k-slice
    const int ksl  = tid >> 6;          // 0..7
    const int sub  = tid & 63;
    const int rowg = sub >> 4;          // 0..3 -> rows rowg+4i
    const int cpg  = sub & 15;          // colpairs cpg, cpg+16
    // epilogue mapping (first 256 threads)
    const int col = tid & 63;
    const int jj  = (tid >> 6) & 3;

    // ---------- init ----------
    for (int i = tid; i < 16 * 512; i += TPB) {
        int r = i >> 9, k = i & 511;
        int grow = 512 * (r >> 2) + j0 + (r & 3);
        s.Whh[r * WHH_STR + k] = whh[(size_t)grow * 512 + k];
    }
    for (int i = tid; i < 16 * 256; i += TPB) {
        int r = i >> 8, k = i & 255;
        int grow = 512 * (r >> 2) + j0 + (r & 3);
        s.Wih[r * WIH_STR + k] = wih[(size_t)grow * 256 + k];
    }
    if (tid < 16) {
        int grow = 512 * (tid >> 2) + j0 + (tid & 3);
        s.bias16[tid] = bias[grow];
        s.gi[tid] = gih[grow]; s.bi[tid] = bih[grow];
        s.gh[tid] = ghh[grow]; s.bh[tid] = bhh[grow];
    }
    if (tid < 4) { s.gc[tid] = gcc[j0 + tid]; s.bc[tid] = bcc[j0 + tid]; }
    if (tid < 256) g_h[0][(j0 + jj) * BSZ + col] = 0.0f;

    float c_reg = 0.0f;

    grid_barrier();

    // ---------- time loop ----------
    for (int t = 0; t < T_STEPS; ++t) {
        const int p = t & 1;
        const float* __restrict__ hsrc = g_h[p];

        // async: x_t (buf lower 64KB), h upper half (buf upper 64KB)
        {
            const float* xg = x + (size_t)t * (ISZ * BSZ);
            #pragma unroll
            for (int i = 0; i < 8; ++i) {
                int o = (tid + i * TPB) * 4;
                cp_async16(&s.buf[o], xg + o);
            }
            cp_commit();
            #pragma unroll
            for (int i = 0; i < 8; ++i) {
                int o = 16384 + (tid + i * TPB) * 4;
                cp_async16(&s.buf[o], hsrc + o);
            }
            cp_commit();
        }
        cp_wait<1>();
        __syncthreads();

        // ---------- x-phase: b = Wih @ x_t ----------
        ull acc[4][2];
        #pragma unroll
        for (int i = 0; i < 4; ++i) { acc[i][0] = 0ULL; acc[i][1] = 0ULL; }
        dot_phase<ISZ / KS, WIH_STR>(acc, s.Wih, s.buf, ksl * (ISZ / KS), rowg, cpg);
        __syncthreads();          // x reads done -> lower buf reusable

        // async: h lower half (overlaps b reduction)
        #pragma unroll
        for (int i = 0; i < 8; ++i) {
            int o = (tid + i * TPB) * 4;
            cp_async16(&s.buf[o], hsrc + o);
        }
        cp_commit();

        store_partials(s, acc, ksl, rowg, cpg);
        __syncthreads();
        reduce_partials(s, s.bRed, tid);
        cp_wait<0>();
        __syncthreads();          // full h present, red consumable again

        // ---------- h-phase: a = Whh @ h ----------
        #pragma unroll
        for (int i = 0; i < 4; ++i) { acc[i][0] = 0ULL; acc[i][1] = 0ULL; }
        dot_phase<HSZ / KS, WHH_STR>(acc, s.Whh, s.buf, ksl * (HSZ / KS), rowg, cpg);
        __syncthreads();
        store_partials(s, acc, ksl, rowg, cpg);
        __syncthreads();
        reduce_partials(s, s.aRed, tid);
        __syncthreads();

        // ---------- BN stats: warp w -> row w (a and b) ----------
        {
            int w = tid >> 5, ln = tid & 31;
            float a0 = s.aRed[w * 64 + ln], a1 = s.aRed[w * 64 + 32 + ln];
            float b0 = s.bRed[w * 64 + ln], b1 = s.bRed[w * 64 + 32 + ln];
            float sa = a0 + a1, qa = a0 * a0 + a1 * a1;
            float sb = b0 + b1, qb = b0 * b0 + b1 * b1;
            #pragma unroll
            for (int off = 16; off; off >>= 1) {
                sa += __shfl_xor_sync(0xffffffffu, sa, off);
                qa += __shfl_xor_sync(0xffffffffu, qa, off);
                sb += __shfl_xor_sync(0xffffffffu, sb, off);
                qb += __shfl_xor_sync(0xffffffffu, qb, off);
            }
            if (ln == 0) {
                float mu = sa * (1.0f / 64.0f);
                float var = qa * (1.0f / 64.0f) - mu * mu;
                float rs = rsqrtf(var + BN_EPS);
                float sc = rs * s.gh[w];
                s.sa_scale[w] = sc; s.sa_shift[w] = s.bh[w] - mu * sc;
                mu = sb * (1.0f / 64.0f);
                var = qb * (1.0f / 64.0f) - mu * mu;
                rs = rsqrtf(var + BN_EPS);
                sc = rs * s.gi[w];
                s.sb_scale[w] = sc; s.sb_shift[w] = s.bi[w] - mu * sc;
            }
        }
        __syncthreads();

        // ---------- gates, cell update, BN(c), h (first 256 threads) ----------
        float cn = 0.0f, go_ = 0.0f;
        if (tid < 256) {
            float pre[4];
            #pragma unroll
            for (int g = 0; g < 4; ++g) {
                int l = g * 4 + jj;
                float av = s.aRed[l * 64 + col] * s.sa_scale[l] + s.sa_shift[l];
                float bv = s.bRed[l * 64 + col] * s.sb_scale[l] + s.sb_shift[l];
                pre[g] = av + bv + s.bias16[l];
            }
            float gi_ = sigm(pre[0]);
            float gf_ = sigm(pre[1]);
            float gg_ = tanh_fast(pre[2]);
            go_ = sigm(pre[3]);
            cn = gf_ * c_reg + gi_ * gg_;
            c_reg = cn;

            float s1 = cn, s2 = cn * cn;
            #pragma unroll
            for (int off = 16; off; off >>= 1) {
                s1 += __shfl_xor_sync(0xffffffffu, s1, off);
                s2 += __shfl_xor_sync(0xffffffffu, s2, off);
            }
            int w = tid >> 5;
            if ((tid & 31) == 0) { s.csum[w] = s1; s.csq[w] = s2; }
        }
        __syncthreads();
        if (tid < 4) {
            float S = s.csum[2 * tid] + s.csum[2 * tid + 1];
            float Q = s.csq[2 * tid] + s.csq[2 * tid + 1];
            float mu = S * (1.0f / 64.0f);
            float var = Q * (1.0f / 64.0f) - mu * mu;
            float rs = rsqrtf(var + BN_EPS);
            float sc = rs * s.gc[tid];
            s.cscale[tid] = sc; s.cshift[tid] = s.bc[tid] - mu * sc;
        }
        __syncthreads();

        if (tid < 256) {
            float hv = go_ * tanh_fast(cn * s.cscale[jj] + s.cshift[jj]);
            int hrow = j0 + jj;
            g_h[1 - p][hrow * BSZ + col] = hv;
            out[(size_t)t * (HSZ * BSZ) + hrow * BSZ + col] = hv;
        }

        grid_barrier();
    }
}

// ---------------- launch ----------------
extern "C" void kernel_launch(void* const* d_in, const int* in_sizes, int n_in,
                              void* d_out, int out_size) {
    const float* x    = (const float*)d_in[0];
    const float* wih  = (const float*)d_in[1];
    const float* whh  = (const float*)d_in[2];
    const float* bias = (const float*)d_in[3];
    const float* gih  = (const float*)d_in[4];
    const float* bih  = (const float*)d_in[5];
    const float* ghh  = (const float*)d_in[6];
    const float* bhh  = (const float*)d_in[7];
    const float* gcc  = (const float*)d_in[8];
    const float* bcc  = (const float*)d_in[9];
    float* out = (float*)d_out;

    cudaFuncSetAttribute(bn_lstm_kernel,
                         cudaFuncAttributeMaxDynamicSharedMemorySize,
                         (int)sizeof(Smem));
    bn_lstm_kernel<<<NB, TPB, sizeof(Smem)>>>(x, wih, whh, bias, gih, bih,
                                              ghh, bhh, gcc, bcc, out);
}

// round 9
// speedup vs baseline: 1.3354x; 1.3354x over previous
#include <cuda_runtime.h>
#include <math.h>
#include <stdint.h>

#define T_STEPS 2048
#define ISZ 256
#define HSZ 512
#define BSZ 64
#define NB 128
#define TPB 256
#define BN_EPS 1e-5f

// ---- SMEM layout (bytes) ----
// pre-phase:
#define SM_PW 0          // 128 rows x 260 floats = 133120 B
#define SM_PX 133120     // 256 rows x 72 floats  = 73728 B  -> end 206848
// recurrent phase (overlaps pre-phase region; phases separated by grid barrier):
#define SM_H      0      // 512 rows x 72 floats = 147456 B
#define SM_W      147456 // 16 rows x 516 floats = 33024 B -> 180480
#define SM_SPILL  180480 // 16 rows x 68 floats  = 4352 B  -> 184832
#define SM_BNB    184832 // 16 x 64 floats       = 4096 B  -> 188928
// params (outside both regions):
#define SM_PAR    206848
#define SMEM_BYTES 207872

#define SPILL_STR 68

struct Par {
    float sca[16], shf[16];
    float gi[16], bi[16], gh[16], bh[16], bias16[16];
    float gc[4], bc[4];
    float csum[8], csq[8], cscale[4], cshift[4];
};

// ---- device globals (static, no allocation) ----
__device__ float g_h[2][HSZ * BSZ];          // h, natural [hidden][batch]
__device__ float g_bnb[268435456];           // [t][2048 rows][64]: BN(Wih@x)+bias (1 GB)
__device__ unsigned long long g_arrive = 0ULL;
__device__ volatile unsigned long long g_release = 0ULL;

// ---- helpers ----
__device__ __forceinline__ void cp_async16(void* smem_dst, const void* gsrc) {
    unsigned s;
    asm("{ .reg .u64 t; cvta.to.shared.u64 t, %1; cvt.u32.u64 %0, t; }"
        : "=r"(s) : "l"(smem_dst));
    asm volatile("cp.async.cg.shared.global [%0], [%1], 16;" :: "r"(s), "l"(gsrc));
}
__device__ __forceinline__ void cp_commit() { asm volatile("cp.async.commit_group;"); }
template <int N>
__device__ __forceinline__ void cp_wait() { asm volatile("cp.async.wait_group %0;" :: "n"(N)); }

// m16n8k8 tf32 HMMA (arch-agnostic PTX, works on plain sm_103 target)
__device__ __forceinline__ void mma8(float* d, uint32_t a0, uint32_t a1, uint32_t a2,
                                     uint32_t a3, uint32_t b0, uint32_t b1) {
    asm volatile(
        "mma.sync.aligned.m16n8k8.row.col.f32.tf32.tf32.f32 "
        "{%0,%1,%2,%3}, {%4,%5,%6,%7}, {%8,%9}, {%0,%1,%2,%3};"
        : "+f"(d[0]), "+f"(d[1]), "+f"(d[2]), "+f"(d[3])
        : "r"(a0), "r"(a1), "r"(a2), "r"(a3), "r"(b0), "r"(b1));
}
__device__ __forceinline__ uint32_t fb(float v) { return __float_as_uint(v); }

__device__ __forceinline__ float sigm(float x) { return 1.0f / (1.0f + __expf(-x)); }
__device__ __forceinline__ float tanh_fast(float x) {
    return 2.0f / (1.0f + __expf(-2.0f * x)) - 1.0f;
}

__device__ __forceinline__ void grid_barrier() {
    __syncthreads();
    if (threadIdx.x == 0) {
        __threadfence();
        unsigned long long a = atomicAdd(&g_arrive, 1ULL);
        unsigned long long target = (a / NB + 1ULL) * NB;
        if (a % NB == NB - 1) {
            __threadfence();
            g_release = target;
        } else {
            while (g_release < target) { }
        }
    }
    __syncthreads();
}

// ---------------- kernel ----------------
__global__ void __launch_bounds__(TPB, 1)
bn_lstm_mma(const float* __restrict__ x,
            const float* __restrict__ wih,
            const float* __restrict__ whh,
            const float* __restrict__ bias,
            const float* __restrict__ gih, const float* __restrict__ bih,
            const float* __restrict__ ghh, const float* __restrict__ bhh,
            const float* __restrict__ gcc, const float* __restrict__ bcc,
            float* __restrict__ out)
{
    extern __shared__ char sm[];
    Par* P = (Par*)(sm + SM_PAR);

    const int tid  = threadIdx.x;
    const int wid  = tid >> 5;
    const int lane = tid & 31;
    const int bid  = blockIdx.x;
    const int j0   = 4 * bid;
    const int gq   = lane >> 2;       // fragment row group 0..7
    const int tq   = lane & 3;        // fragment k/col group 0..3
    // epilogue mapping
    const int col = tid & 63;
    const int jj  = (tid >> 6) & 3;

    // zero h[0] (own rows)
    g_h[0][(j0 + jj) * BSZ + col] = 0.0f;

    // ================= PRE-PHASE: g_bnb[t] = BN(Wih @ x_t) + bias =================
    {
        float* PW = (float*)(sm + SM_PW);
        float* PX = (float*)(sm + SM_PX);
        for (int mc = 0; mc < 16; ++mc) {
            const int rbase = mc * 128;
            __syncthreads();   // previous iter done with PW/PX
            // load W chunk [128 x 256] -> stride 260
            #pragma unroll
            for (int i = 0; i < 32; ++i) {
                int e = tid + i * TPB;            // float4 index
                int r = e >> 6, q = e & 63;
                cp_async16(&PW[r * 260 + q * 4],
                           wih + ((size_t)(rbase + r)) * 256 + q * 4);
            }
            cp_commit();

            for (int tt = 0; tt < 16; ++tt) {
                const int t = bid * 16 + tt;
                // load x_t [256 x 64] -> stride 72
                #pragma unroll
                for (int i = 0; i < 16; ++i) {
                    int e = tid + i * TPB;
                    int r = e >> 4, q = e & 15;
                    cp_async16(&PX[r * 72 + q * 4],
                               x + ((size_t)t * 256 + r) * 64 + q * 4);
                }
                cp_commit();
                cp_wait<0>();
                __syncthreads();

                // warp wid -> M-tile rows rbase + wid*16 + {gq, gq+8}
                float acc[8][4];
                #pragma unroll
                for (int nt = 0; nt < 8; ++nt)
                    #pragma unroll
                    for (int i = 0; i < 4; ++i) acc[nt][i] = 0.0f;

                const float* WA = PW + (wid * 16) * 260;
                #pragma unroll 4
                for (int ks = 0; ks < 32; ++ks) {
                    int k = ks * 8 + tq;
                    uint32_t a0 = fb(WA[gq * 260 + k]);
                    uint32_t a1 = fb(WA[(gq + 8) * 260 + k]);
                    uint32_t a2 = fb(WA[gq * 260 + k + 4]);
                    uint32_t a3 = fb(WA[(gq + 8) * 260 + k + 4]);
                    #pragma unroll
                    for (int nt = 0; nt < 8; ++nt) {
                        uint32_t b0 = fb(PX[k * 72 + nt * 8 + gq]);
                        uint32_t b1 = fb(PX[(k + 4) * 72 + nt * 8 + gq]);
                        mma8(acc[nt], a0, a1, a2, a3, b0, b1);
                    }
                }

                // BN over batch, warp-local (thread -> rows row0, row1; 16 cols each)
                int row0 = rbase + wid * 16 + gq;
                int row1 = row0 + 8;
                float s0 = 0, q0 = 0, s1 = 0, q1 = 0;
                #pragma unroll
                for (int nt = 0; nt < 8; ++nt) {
                    s0 += acc[nt][0] + acc[nt][1];
                    q0 += acc[nt][0] * acc[nt][0] + acc[nt][1] * acc[nt][1];
                    s1 += acc[nt][2] + acc[nt][3];
                    q1 += acc[nt][2] * acc[nt][2] + acc[nt][3] * acc[nt][3];
                }
                #pragma unroll
                for (int off = 1; off < 4; off <<= 1) {
                    s0 += __shfl_xor_sync(0xffffffffu, s0, off);
                    q0 += __shfl_xor_sync(0xffffffffu, q0, off);
                    s1 += __shfl_xor_sync(0xffffffffu, s1, off);
                    q1 += __shfl_xor_sync(0xffffffffu, q1, off);
                }
                float mu0 = s0 * (1.0f / 64.0f);
                float v0  = q0 * (1.0f / 64.0f) - mu0 * mu0;
                float sc0 = rsqrtf(v0 + BN_EPS) * gih[row0];
                float sh0 = bih[row0] - mu0 * sc0 + bias[row0];
                float mu1 = s1 * (1.0f / 64.0f);
                float v1  = q1 * (1.0f / 64.0f) - mu1 * mu1;
                float sc1 = rsqrtf(v1 + BN_EPS) * gih[row1];
                float sh1 = bih[row1] - mu1 * sc1 + bias[row1];

                float* d0 = g_bnb + ((size_t)t * 2048 + row0) * 64;
                float* d1 = g_bnb + ((size_t)t * 2048 + row1) * 64;
                #pragma unroll
                for (int nt = 0; nt < 8; ++nt) {
                    float2 w0 = make_float2(acc[nt][0] * sc0 + sh0,
                                            acc[nt][1] * sc0 + sh0);
                    float2 w1 = make_float2(acc[nt][2] * sc1 + sh1,
                                            acc[nt][3] * sc1 + sh1);
                    *(float2*)&d0[nt * 8 + 2 * tq] = w0;
                    *(float2*)&d1[nt * 8 + 2 * tq] = w1;
                }
                __syncthreads();   // before next x overwrite
            }
        }
    }

    grid_barrier();

    // ---------- load params + Whh (rows l = gate*4 + r) ----------
    float* H     = (float*)(sm + SM_H);
    float* W     = (float*)(sm + SM_W);
    float* SPILL = (float*)(sm + SM_SPILL);
    float* BNB   = (float*)(sm + SM_BNB);

    if (tid < 16) {
        int grow = 512 * (tid >> 2) + j0 + (tid & 3);
        P->gh[tid] = ghh[grow]; P->bh[tid] = bhh[grow];
    }
    if (tid < 4) { P->gc[tid] = gcc[j0 + tid]; P->bc[tid] = bcc[j0 + tid]; }
    for (int i = tid; i < 16 * 512; i += TPB) {
        int l = i >> 9, k = i & 511;
        int grow = 512 * (l >> 2) + j0 + (l & 3);
        W[l * 516 + k] = whh[(size_t)grow * 512 + k];
    }
    __syncthreads();

    // ================= recurrent loop =================
    float c_reg = 0.0f;
    for (int t = 0; t < T_STEPS; ++t) {
        const int p = t & 1;
        const float* __restrict__ hsrc = g_h[p];

        // cp.async h [512 x 64] -> stride 72 (512 rows x 16 float4 = 8192 float4)
        #pragma unroll
        for (int i = 0; i < 32; ++i) {
            int e = tid + i * TPB;
            int r = e >> 4, q = e & 15;
            cp_async16(&H[r * 72 + q * 4], hsrc + r * 64 + q * 4);
        }
        // cp.async bnb tile [16 x 64]
        {
            int l = tid >> 4, q = tid & 15;
            int grow = 512 * (l >> 2) + j0 + (l & 3);
            cp_async16(&BNB[l * 64 + q * 4],
                       g_bnb + ((size_t)t * 2048 + grow) * 64 + q * 4);
        }
        cp_commit();
        cp_wait<0>();
        __syncthreads();

        // a = Whh @ h : warp wid -> N-tile (cols wid*8..wid*8+7), K = 64 slices
        float acc[4] = {0.0f, 0.0f, 0.0f, 0.0f};
        #pragma unroll 4
        for (int ks = 0; ks < 64; ++ks) {
            int k = ks * 8 + tq;
            uint32_t a0 = fb(W[gq * 516 + k]);
            uint32_t a1 = fb(W[(gq + 8) * 516 + k]);
            uint32_t a2 = fb(W[gq * 516 + k + 4]);
            uint32_t a3 = fb(W[(gq + 8) * 516 + k + 4]);
            uint32_t b0 = fb(H[k * 72 + wid * 8 + gq]);
            uint32_t b1 = fb(H[(k + 4) * 72 + wid * 8 + gq]);
            mma8(acc, a0, a1, a2, a3, b0, b1);
        }
        // spill D: rows {gq, gq+8}, cols wid*8 + 2tq + {0,1}
        *(float2*)&SPILL[gq * SPILL_STR + wid * 8 + 2 * tq] =
            make_float2(acc[0], acc[1]);
        *(float2*)&SPILL[(gq + 8) * SPILL_STR + wid * 8 + 2 * tq] =
            make_float2(acc[2], acc[3]);
        __syncthreads();

        // BN(a): warp w -> rows 2w, 2w+1
        {
            #pragma unroll
            for (int rr = 0; rr < 2; ++rr) {
                int r = 2 * wid + rr;
                float a0 = SPILL[r * SPILL_STR + lane];
                float a1 = SPILL[r * SPILL_STR + 32 + lane];
                float sa = a0 + a1, qa = a0 * a0 + a1 * a1;
                #pragma unroll
                for (int off = 16; off; off >>= 1) {
                    sa += __shfl_xor_sync(0xffffffffu, sa, off);
                    qa += __shfl_xor_sync(0xffffffffu, qa, off);
                }
                if (lane == 0) {
                    float mu = sa * (1.0f / 64.0f);
                    float var = qa * (1.0f / 64.0f) - mu * mu;
                    float sc = rsqrtf(var + BN_EPS) * P->gh[r];
                    P->sca[r] = sc; P->shf[r] = P->bh[r] - mu * sc;
                }
            }
        }
        __syncthreads();

        // gates + cell + BN(c) + h
        float pre[4];
        #pragma unroll
        for (int g = 0; g < 4; ++g) {
            int l = g * 4 + jj;
            pre[g] = SPILL[l * SPILL_STR + col] * P->sca[l] + P->shf[l]
                   + BNB[l * 64 + col];
        }
        float gi_ = sigm(pre[0]);
        float gf_ = sigm(pre[1]);
        float gg_ = tanh_fast(pre[2]);
        float go_ = sigm(pre[3]);
        float cn = gf_ * c_reg + gi_ * gg_;
        c_reg = cn;

        {
            float s1 = cn, s2 = cn * cn;
            #pragma unroll
            for (int off = 16; off; off >>= 1) {
                s1 += __shfl_xor_sync(0xffffffffu, s1, off);
                s2 += __shfl_xor_sync(0xffffffffu, s2, off);
            }
            if (lane == 0) { P->csum[wid] = s1; P->csq[wid] = s2; }
        }
        __syncthreads();
        if (tid < 4) {
            float S = P->csum[2 * tid] + P->csum[2 * tid + 1];
            float Q = P->csq[2 * tid] + P->csq[2 * tid + 1];
            float mu = S * (1.0f / 64.0f);
            float var = Q * (1.0f / 64.0f) - mu * mu;
            float sc = rsqrtf(var + BN_EPS) * P->gc[tid];
            P->cscale[tid] = sc; P->cshift[tid] = P->bc[tid] - mu * sc;
        }
        __syncthreads();

        float hv = go_ * tanh_fast(cn * P->cscale[jj] + P->cshift[jj]);
        g_h[1 - p][(j0 + jj) * BSZ + col] = hv;
        out[(size_t)t * (HSZ * BSZ) + (j0 + jj) * BSZ + col] = hv;

        grid_barrier();
    }
}

// ---------------- launch ----------------
extern "C" void kernel_launch(void* const* d_in, const int* in_sizes, int n_in,
                              void* d_out, int out_size) {
    const float* x    = (const float*)d_in[0];
    const float* wih  = (const float*)d_in[1];
    const float* whh  = (const float*)d_in[2];
    const float* bias = (const float*)d_in[3];
    const float* gih  = (const float*)d_in[4];
    const float* bih  = (const float*)d_in[5];
    const float* ghh  = (const float*)d_in[6];
    const float* bhh  = (const float*)d_in[7];
    const float* gcc  = (const float*)d_in[8];
    const float* bcc  = (const float*)d_in[9];
    float* out = (float*)d_out;

    cudaFuncSetAttribute(bn_lstm_mma,
                         cudaFuncAttributeMaxDynamicSharedMemorySize, SMEM_BYTES);
    bn_lstm_mma<<<NB, TPB, SMEM_BYTES>>>(x, wih, whh, bias, gih, bih,
                                         ghh, bhh, gcc, bcc, out);
}

// round 10
// speedup vs baseline: 1.6710x; 1.2513x over previous
#include <cuda_runtime.h>
#include <cuda_fp16.h>
#include <math.h>
#include <stdint.h>

#define T_STEPS 2048
#define ISZ 256
#define HSZ 512
#define BSZ 64
#define NB 128
#define TPB 256
#define BN_EPS 1e-5f

// ---- SMEM layout (bytes) ----
// pre-phase:
#define SM_PW 0          // 128 rows x 260 floats = 133120 B
#define SM_PX 133120     // 256 rows x 72 floats  = 73728 B  -> end 206848
// recurrent phase (overlaps pre-phase region; separated by grid barrier):
#define SM_H      0      // 64 cols x 520 halves (260 words) = 66560 B
#define SM_WP     66560  // permuted W fragments: 4096 words = 16384 B -> 82944
#define SM_SPILL  82944  // 16 rows x 68 floats = 4352 B -> 87296
#define SM_BNB    87296  // 16 x 64 floats = 4096 B -> 91392
// params:
#define SM_PAR    206848
#define SMEM_BYTES 207872

#define SPILL_STR 68
#define HSTR_W 260        // H row stride in 32-bit words (520 halves)

struct Par {
    float sca[16], shf[16];
    float gh[16], bh[16];
    float gc[4], bc[4];
    float csum[8], csq[8], cscale[4], cshift[4];
};

// ---- device globals (static, no allocation) ----
__device__ __half g_h16[2][BSZ * HSZ];       // h fp16, batch-major [col][hidden]
__device__ float g_bnb[268435456];           // [t][2048 rows][64]: BN(Wih@x)+bias
__device__ unsigned long long g_arrive = 0ULL;
__device__ volatile unsigned long long g_release = 0ULL;

// ---- helpers ----
__device__ __forceinline__ void cp_async16(void* smem_dst, const void* gsrc) {
    unsigned s;
    asm("{ .reg .u64 t; cvta.to.shared.u64 t, %1; cvt.u32.u64 %0, t; }"
        : "=r"(s) : "l"(smem_dst));
    asm volatile("cp.async.cg.shared.global [%0], [%1], 16;" :: "r"(s), "l"(gsrc));
}
__device__ __forceinline__ void cp_commit() { asm volatile("cp.async.commit_group;"); }
template <int N>
__device__ __forceinline__ void cp_wait() { asm volatile("cp.async.wait_group %0;" :: "n"(N)); }

// m16n8k8 tf32 HMMA (pre-phase)
__device__ __forceinline__ void mma8(float* d, uint32_t a0, uint32_t a1, uint32_t a2,
                                     uint32_t a3, uint32_t b0, uint32_t b1) {
    asm volatile(
        "mma.sync.aligned.m16n8k8.row.col.f32.tf32.tf32.f32 "
        "{%0,%1,%2,%3}, {%4,%5,%6,%7}, {%8,%9}, {%0,%1,%2,%3};"
        : "+f"(d[0]), "+f"(d[1]), "+f"(d[2]), "+f"(d[3])
        : "r"(a0), "r"(a1), "r"(a2), "r"(a3), "r"(b0), "r"(b1));
}
// m16n8k16 f16 HMMA (recurrent loop)
__device__ __forceinline__ void mma16(float* d, uint32_t a0, uint32_t a1, uint32_t a2,
                                      uint32_t a3, uint32_t b0, uint32_t b1) {
    asm volatile(
        "mma.sync.aligned.m16n8k16.row.col.f32.f16.f16.f32 "
        "{%0,%1,%2,%3}, {%4,%5,%6,%7}, {%8,%9}, {%0,%1,%2,%3};"
        : "+f"(d[0]), "+f"(d[1]), "+f"(d[2]), "+f"(d[3])
        : "r"(a0), "r"(a1), "r"(a2), "r"(a3), "r"(b0), "r"(b1));
}
__device__ __forceinline__ uint32_t fb(float v) { return __float_as_uint(v); }

__device__ __forceinline__ float sigm(float x) { return 1.0f / (1.0f + __expf(-x)); }
__device__ __forceinline__ float tanh_fast(float x) {
    return 2.0f / (1.0f + __expf(-2.0f * x)) - 1.0f;
}

__device__ __forceinline__ void grid_barrier() {
    __syncthreads();
    if (threadIdx.x == 0) {
        __threadfence();
        unsigned long long a = atomicAdd(&g_arrive, 1ULL);
        unsigned long long target = (a / NB + 1ULL) * NB;
        if (a % NB == NB - 1) {
            __threadfence();
            g_release = target;
        } else {
            while (g_release < target) { }
        }
    }
    __syncthreads();
}

// ---------------- kernel ----------------
__global__ void __launch_bounds__(TPB, 1)
bn_lstm_mma(const float* __restrict__ x,
            const float* __restrict__ wih,
            const float* __restrict__ whh,
            const float* __restrict__ bias,
            const float* __restrict__ gih, const float* __restrict__ bih,
            const float* __restrict__ ghh, const float* __restrict__ bhh,
            const float* __restrict__ gcc, const float* __restrict__ bcc,
            float* __restrict__ out)
{
    extern __shared__ char sm[];
    Par* P = (Par*)(sm + SM_PAR);

    const int tid  = threadIdx.x;
    const int wid  = tid >> 5;
    const int lane = tid & 31;
    const int bid  = blockIdx.x;
    const int j0   = 4 * bid;
    const int gq   = lane >> 2;       // fragment row group 0..7
    const int tq   = lane & 3;        // fragment k/col group 0..3
    const int col = tid & 63;
    const int jj  = (tid >> 6) & 3;

    // zero h[0] (own rows), fp16 batch-major
    g_h16[0][col * HSZ + j0 + jj] = __float2half(0.0f);

    // ================= PRE-PHASE: g_bnb[t] = BN(Wih @ x_t) + bias =================
    {
        float* PW = (float*)(sm + SM_PW);
        float* PX = (float*)(sm + SM_PX);
        for (int mc = 0; mc < 16; ++mc) {
            const int rbase = mc * 128;
            __syncthreads();
            #pragma unroll
            for (int i = 0; i < 32; ++i) {
                int e = tid + i * TPB;
                int r = e >> 6, q = e & 63;
                cp_async16(&PW[r * 260 + q * 4],
                           wih + ((size_t)(rbase + r)) * 256 + q * 4);
            }
            cp_commit();

            for (int tt = 0; tt < 16; ++tt) {
                const int t = bid * 16 + tt;
                #pragma unroll
                for (int i = 0; i < 16; ++i) {
                    int e = tid + i * TPB;
                    int r = e >> 4, q = e & 15;
                    cp_async16(&PX[r * 72 + q * 4],
                               x + ((size_t)t * 256 + r) * 64 + q * 4);
                }
                cp_commit();
                cp_wait<0>();
                __syncthreads();

                float acc[8][4];
                #pragma unroll
                for (int nt = 0; nt < 8; ++nt)
                    #pragma unroll
                    for (int i = 0; i < 4; ++i) acc[nt][i] = 0.0f;

                const float* WA = PW + (wid * 16) * 260;
                #pragma unroll 4
                for (int ks = 0; ks < 32; ++ks) {
                    int k = ks * 8 + tq;
                    uint32_t a0 = fb(WA[gq * 260 + k]);
                    uint32_t a1 = fb(WA[(gq + 8) * 260 + k]);
                    uint32_t a2 = fb(WA[gq * 260 + k + 4]);
                    uint32_t a3 = fb(WA[(gq + 8) * 260 + k + 4]);
                    #pragma unroll
                    for (int nt = 0; nt < 8; ++nt) {
                        uint32_t b0 = fb(PX[k * 72 + nt * 8 + gq]);
                        uint32_t b1 = fb(PX[(k + 4) * 72 + nt * 8 + gq]);
                        mma8(acc[nt], a0, a1, a2, a3, b0, b1);
                    }
                }

                int row0 = rbase + wid * 16 + gq;
                int row1 = row0 + 8;
                float s0 = 0, q0 = 0, s1 = 0, q1 = 0;
                #pragma unroll
                for (int nt = 0; nt < 8; ++nt) {
                    s0 += acc[nt][0] + acc[nt][1];
                    q0 += acc[nt][0] * acc[nt][0] + acc[nt][1] * acc[nt][1];
                    s1 += acc[nt][2] + acc[nt][3];
                    q1 += acc[nt][2] * acc[nt][2] + acc[nt][3] * acc[nt][3];
                }
                #pragma unroll
                for (int off = 1; off < 4; off <<= 1) {
                    s0 += __shfl_xor_sync(0xffffffffu, s0, off);
                    q0 += __shfl_xor_sync(0xffffffffu, q0, off);
                    s1 += __shfl_xor_sync(0xffffffffu, s1, off);
                    q1 += __shfl_xor_sync(0xffffffffu, q1, off);
                }
                float mu0 = s0 * (1.0f / 64.0f);
                float v0  = q0 * (1.0f / 64.0f) - mu0 * mu0;
                float sc0 = rsqrtf(v0 + BN_EPS) * gih[row0];
                float sh0 = bih[row0] - mu0 * sc0 + bias[row0];
                float mu1 = s1 * (1.0f / 64.0f);
                float v1  = q1 * (1.0f / 64.0f) - mu1 * mu1;
                float sc1 = rsqrtf(v1 + BN_EPS) * gih[row1];
                float sh1 = bih[row1] - mu1 * sc1 + bias[row1];

                float* d0 = g_bnb + ((size_t)t * 2048 + row0) * 64;
                float* d1 = g_bnb + ((size_t)t * 2048 + row1) * 64;
                #pragma unroll
                for (int nt = 0; nt < 8; ++nt) {
                    *(float2*)&d0[nt * 8 + 2 * tq] =
                        make_float2(acc[nt][0] * sc0 + sh0, acc[nt][1] * sc0 + sh0);
                    *(float2*)&d1[nt * 8 + 2 * tq] =
                        make_float2(acc[nt][2] * sc1 + sh1, acc[nt][3] * sc1 + sh1);
                }
                __syncthreads();
            }
        }
    }

    grid_barrier();

    // ---------- recurrent-phase setup ----------
    __half*   H16  = (__half*)(sm + SM_H);
    uint32_t* H32  = (uint32_t*)(sm + SM_H);
    uint32_t* WP32 = (uint32_t*)(sm + SM_WP);
    float* SPILL   = (float*)(sm + SM_SPILL);
    float* BNB     = (float*)(sm + SM_BNB);

    if (tid < 16) {
        int grow = 512 * (tid >> 2) + j0 + (tid & 3);
        P->gh[tid] = ghh[grow]; P->bh[tid] = bhh[grow];
    }
    if (tid < 4) { P->gc[tid] = gcc[j0 + tid]; P->bc[tid] = bcc[j0 + tid]; }

    // permuted W fragments: word i -> (ks, lane, j); one LDS.128 per (ks,lane)
    for (int i = tid; i < 4096; i += TPB) {
        int ks = i >> 7, ln = (i >> 2) & 31, j = i & 3;
        int g2 = ln >> 2, t2 = ln & 3;
        int l  = g2 + 8 * (j & 1);               // local gate row 0..15
        int hc = 16 * ks + 2 * t2 + 8 * (j >> 1); // half-column (k index)
        int grow = 512 * (l >> 2) + j0 + (l & 3);
        __half2 hh = __floats2half2_rn(whh[(size_t)grow * 512 + hc],
                                       whh[(size_t)grow * 512 + hc + 1]);
        WP32[i] = *(uint32_t*)&hh;
    }
    __syncthreads();

    const int nrow260 = (wid * 8 + gq) * HSTR_W;
    const __half* hgbase0 = g_h16[0];
    const __half* hgbase1 = g_h16[1];

    // ================= recurrent loop =================
    float c_reg = 0.0f;
    for (int t = 0; t < T_STEPS; ++t) {
        const int p = t & 1;
        const __half* __restrict__ hsrc = p ? hgbase1 : hgbase0;

        // 4 chunks of h (k halves [c*128,(c+1)*128) per batch-col), separate groups
        #pragma unroll
        for (int c = 0; c < 4; ++c) {
            #pragma unroll
            for (int i = 0; i < 4; ++i) {
                int e = tid + i * TPB;          // 0..1023
                int cc = e >> 4, q = e & 15;
                cp_async16(H16 + cc * 520 + c * 128 + q * 8,
                           hsrc + cc * 512 + c * 128 + q * 8);
            }
            if (c == 3) {
                int l = tid >> 4, q = tid & 15;
                int grow = 512 * (l >> 2) + j0 + (l & 3);
                cp_async16(&BNB[l * 64 + q * 4],
                           g_bnb + ((size_t)t * 2048 + grow) * 64 + q * 4);
            }
            cp_commit();
        }

        // a = Whh @ h, pipelined over chunks; two accumulator chains
        float ac0[4] = {0, 0, 0, 0}, ac1[4] = {0, 0, 0, 0};
        #define DO_CHUNK(C)                                                     \
        {                                                                       \
            _Pragma("unroll")                                                   \
            for (int s2 = 0; s2 < 8; ++s2) {                                    \
                int ks = 8 * (C) + s2;                                          \
                uint4 aw = *(const uint4*)(WP32 + (ks * 32 + lane) * 4);        \
                uint32_t b0 = H32[nrow260 + 8 * ks + tq];                       \
                uint32_t b1 = H32[nrow260 + 8 * ks + tq + 4];                   \
                mma16((s2 & 1) ? ac1 : ac0, aw.x, aw.y, aw.z, aw.w, b0, b1);    \
            }                                                                   \
        }
        cp_wait<3>(); __syncthreads(); DO_CHUNK(0);
        cp_wait<2>(); __syncthreads(); DO_CHUNK(1);
        cp_wait<1>(); __syncthreads(); DO_CHUNK(2);
        cp_wait<0>(); __syncthreads(); DO_CHUNK(3);
        #undef DO_CHUNK

        float acc[4];
        #pragma unroll
        for (int i = 0; i < 4; ++i) acc[i] = ac0[i] + ac1[i];

        // spill D: rows {gq, gq+8}, cols wid*8 + 2tq + {0,1}
        *(float2*)&SPILL[gq * SPILL_STR + wid * 8 + 2 * tq] =
            make_float2(acc[0], acc[1]);
        *(float2*)&SPILL[(gq + 8) * SPILL_STR + wid * 8 + 2 * tq] =
            make_float2(acc[2], acc[3]);
        __syncthreads();

        // BN(a): warp w -> rows 2w, 2w+1
        {
            #pragma unroll
            for (int rr = 0; rr < 2; ++rr) {
                int r = 2 * wid + rr;
                float a0 = SPILL[r * SPILL_STR + lane];
                float a1 = SPILL[r * SPILL_STR + 32 + lane];
                float sa = a0 + a1, qa = a0 * a0 + a1 * a1;
                #pragma unroll
                for (int off = 16; off; off >>= 1) {
                    sa += __shfl_xor_sync(0xffffffffu, sa, off);
                    qa += __shfl_xor_sync(0xffffffffu, qa, off);
                }
                if (lane == 0) {
                    float mu = sa * (1.0f / 64.0f);
                    float var = qa * (1.0f / 64.0f) - mu * mu;
                    float sc = rsqrtf(var + BN_EPS) * P->gh[r];
                    P->sca[r] = sc; P->shf[r] = P->bh[r] - mu * sc;
                }
            }
        }
        __syncthreads();

        // gates + cell + BN(c) + h
        float pre[4];
        #pragma unroll
        for (int g = 0; g < 4; ++g) {
            int l = g * 4 + jj;
            pre[g] = SPILL[l * SPILL_STR + col] * P->sca[l] + P->shf[l]
                   + BNB[l * 64 + col];
        }
        float gi_ = sigm(pre[0]);
        float gf_ = sigm(pre[1]);
        float gg_ = tanh_fast(pre[2]);
        float go_ = sigm(pre[3]);
        float cn = gf_ * c_reg + gi_ * gg_;
        c_reg = cn;

        {
            float s1 = cn, s2 = cn * cn;
            #pragma unroll
            for (int off = 16; off; off >>= 1) {
                s1 += __shfl_xor_sync(0xffffffffu, s1, off);
                s2 += __shfl_xor_sync(0xffffffffu, s2, off);
            }
            if (lane == 0) { P->csum[wid] = s1; P->csq[wid] = s2; }
        }
        __syncthreads();
        if (tid < 4) {
            float S = P->csum[2 * tid] + P->csum[2 * tid + 1];
            float Q = P->csq[2 * tid] + P->csq[2 * tid + 1];
            float mu = S * (1.0f / 64.0f);
            float var = Q * (1.0f / 64.0f) - mu * mu;
            float sc = rsqrtf(var + BN_EPS) * P->gc[tid];
            P->cscale[tid] = sc; P->cshift[tid] = P->bc[tid] - mu * sc;
        }
        __syncthreads();

        float hv = go_ * tanh_fast(cn * P->cscale[jj] + P->cshift[jj]);
        g_h16[1 - p][col * HSZ + j0 + jj] = __float2half(hv);
        out[(size_t)t * (HSZ * BSZ) + (j0 + jj) * BSZ + col] = hv;

        grid_barrier();
    }
}

// ---------------- launch ----------------
extern "C" void kernel_launch(void* const* d_in, const int* in_sizes, int n_in,
                              void* d_out, int out_size) {
    const float* x    = (const float*)d_in[0];
    const float* wih  = (const float*)d_in[1];
    const float* whh  = (const float*)d_in[2];
    const float* bias = (const float*)d_in[3];
    const float* gih  = (const float*)d_in[4];
    const float* bih  = (const float*)d_in[5];
    const float* ghh  = (const float*)d_in[6];
    const float* bhh  = (const float*)d_in[7];
    const float* gcc  = (const float*)d_in[8];
    const float* bcc  = (const float*)d_in[9];
    float* out = (float*)d_out;

    cudaFuncSetAttribute(bn_lstm_mma,
                         cudaFuncAttributeMaxDynamicSharedMemorySize, SMEM_BYTES);
    bn_lstm_mma<<<NB, TPB, SMEM_BYTES>>>(x, wih, whh, bias, gih, bih,
                                         ghh, bhh, gcc, bcc, out);
}